// round 12
// baseline (speedup 1.0000x reference)
#include <cuda_runtime.h>
#include <math.h>

#define N_FFT 512
#define HOP 128
#define NBINS 257
#define ROWSTRIDE 260
#define MAX_FRAMES 32769
#define FPC 4
#define MAX_CTAS ((MAX_FRAMES + FPC - 1) / FPC)
#define TWO_PI_F 6.28318530717958647692f

__device__ float g_last[(size_t)MAX_CTAS * ROWSTRIDE];
__device__ unsigned int g_flag[MAX_CTAS];   // zero-init; consumer-reset each call
__device__ double g_acc[3];                 // zero-init; ticket-winner cleans
__device__ unsigned int g_done;             // ticket; winner cleans

// ---------------- packed complex (f32x2) helpers ----------------
typedef unsigned long long cplx;     // lo = re, hi = im

__device__ __forceinline__ cplx cpack(float re, float im) {
    cplx r; asm("mov.b64 %0, {%1, %2};" : "=l"(r) : "f"(re), "f"(im)); return r;
}
__device__ __forceinline__ void cunpack(cplx a, float& re, float& im) {
    asm("mov.b64 {%0, %1}, %2;" : "=f"(re), "=f"(im) : "l"(a));
}
__device__ __forceinline__ cplx cswap(cplx a) {
    cplx r;
    asm("{\n\t.reg .f32 lo, hi;\n\tmov.b64 {lo, hi}, %1;\n\tmov.b64 %0, {hi, lo};\n\t}"
        : "=l"(r) : "l"(a));
    return r;
}
__device__ __forceinline__ cplx cadd2(cplx a, cplx b) {
    cplx r; asm("add.rn.f32x2 %0, %1, %2;" : "=l"(r) : "l"(a), "l"(b)); return r;
}
__device__ __forceinline__ cplx cmul2(cplx a, cplx b) {
    cplx r; asm("mul.rn.f32x2 %0, %1, %2;" : "=l"(r) : "l"(a), "l"(b)); return r;
}
__device__ __forceinline__ cplx cfma2(cplx a, cplx b, cplx c) {
    cplx r; asm("fma.rn.f32x2 %0, %1, %2, %3;" : "=l"(r) : "l"(a), "l"(b), "l"(c)); return r;
}
__device__ __forceinline__ float fneg(float x) {
    return __int_as_float(__float_as_int(x) ^ 0x80000000);
}

__device__ __forceinline__ int reflect_idx(int j, int T) {
    j = abs(j);
    if (j >= T) j = 2 * T - 2 - j;
    return j;
}

__device__ __forceinline__ float anti_wrap(float x) {
    return fabsf(fmaf(-rintf(x * (1.0f / TWO_PI_F)), TWO_PI_F, x));
}

// fast atan2: deg-11 odd minimax poly, max abs err ~2e-6
__device__ __forceinline__ float fast_atan2f(float y, float x) {
    float ax = fabsf(x), ay = fabsf(y);
    float mx = fmaxf(ax, ay), mn = fminf(ax, ay);
    float a = __fdividef(mn, mx);
    float s = a * a;
    float r = -0.0117212f;
    r = fmaf(r, s,  0.05265332f);
    r = fmaf(r, s, -0.11643287f);
    r = fmaf(r, s,  0.19354346f);
    r = fmaf(r, s, -0.33262347f);
    r = fmaf(r, s,  0.99997726f);
    r = r * a;
    if (ay > ax) r = 1.57079632679f - r;
    if (x < 0.0f) r = 3.14159265359f - r;
    return copysignf(r, y);
}

__device__ __forceinline__ void cmuls(float ar, float ai, float br, float bi,
                                      float& cr, float& ci) {
    cr = fmaf(ar, br, -ai * bi);
    ci = fmaf(ar, bi,  ai * br);
}

__device__ __forceinline__ void build7(float w1r, float w1i,
                                       float wr[8], float wi[8]) {
    wr[1] = w1r; wi[1] = w1i;
    cmuls(w1r, w1i, w1r, w1i, wr[2], wi[2]);
    cmuls(wr[2], wi[2], w1r, w1i, wr[3], wi[3]);
    cmuls(wr[2], wi[2], wr[2], wi[2], wr[4], wi[4]);
    cmuls(wr[3], wi[3], wr[2], wi[2], wr[5], wi[5]);
    cmuls(wr[3], wi[3], wr[3], wi[3], wr[6], wi[6]);
    cmuls(wr[4], wi[4], wr[3], wi[3], wr[7], wi[7]);
}

__device__ __forceinline__ void dft8p(cplx x[8], cplx NEG1, cplx PMI, cplx CC) {
    cplx s0 = cadd2(x[0], x[4]);
    cplx s1 = cadd2(x[1], x[5]);
    cplx s2 = cadd2(x[2], x[6]);
    cplx s3 = cadd2(x[3], x[7]);
    cplx u0 = cfma2(x[4], NEG1, x[0]);
    cplx u1 = cfma2(x[5], NEG1, x[1]);
    cplx u2 = cfma2(x[6], NEG1, x[2]);
    cplx u3 = cfma2(x[7], NEG1, x[3]);

    cplx t1 = cmul2(CC, cfma2(cswap(u1), PMI, u1));
    cplx t2 = cmul2(cswap(u2), PMI);
    cplx t3 = cmul2(CC, cfma2(u3, NEG1, cmul2(cswap(u3), PMI)));

    cplx e0 = cadd2(s0, s2);
    cplx e2 = cfma2(s2, NEG1, s0);
    cplx e1 = cadd2(s1, s3);
    cplx d13 = cfma2(s3, NEG1, s1);
    cplx e3 = cmul2(cswap(d13), PMI);
    x[0] = cadd2(e0, e1);
    x[4] = cfma2(e1, NEG1, e0);
    x[2] = cadd2(e2, e3);
    x[6] = cfma2(e3, NEG1, e2);

    cplx o0 = cadd2(u0, t2);
    cplx o2 = cfma2(t2, NEG1, u0);
    cplx o1 = cadd2(t1, t3);
    cplx d13b = cfma2(t3, NEG1, t1);
    cplx o3 = cmul2(cswap(d13b), PMI);
    x[1] = cadd2(o0, o1);
    x[5] = cfma2(o1, NEG1, o0);
    x[3] = cadd2(o2, o3);
    x[7] = cfma2(o3, NEG1, o2);
}

__device__ __forceinline__ cplx ctws(cplx x, float wr, float wi) {
    cplx wrr = cpack(wr, wr);
    cplx wim = cpack(fneg(wi), wi);
    return cfma2(cswap(x), wim, cmul2(x, wrr));
}

__device__ __forceinline__ int sw_addr(int f) {
    return f ^ ((f >> 3) & 7);
}

// 4 frames per 256-thread CTA; radix-8^3 packed-register FFT; ALL losses fused
// (cross-CTA iaf via decoupled look-back on g_last; finalize via ticket).
__global__ __launch_bounds__(256) void fft_phase_kernel(
    const float* __restrict__ yd, const float* __restrict__ td,
    float* __restrict__ out, int T, int n_frames, int n_cta)
{
    __shared__ cplx sZ[FPC][592];
    __shared__ float dBuf[FPC][260];
    __shared__ float wsum[8][3];

    const int lt = threadIdx.x & 63;
    const int fl = threadIdx.x >> 6;
    const int b = blockIdx.x;
    const int frame = b * FPC + fl;
    const bool active = (frame < n_frames);

    const cplx NEG1 = cpack(-1.0f, -1.0f);
    const cplx PMI  = cpack(1.0f, -1.0f);
    const cplx CC   = cpack(0.70710678118654752440f, 0.70710678118654752440f);

    cplx x[8];

    // ---- load (fast interior path skips all reflect logic) ----
    if (active) {
        const int base = frame * HOP - (N_FFT / 2) + lt;
        if (frame >= 2 && frame * HOP + 256 <= T) {
            const float* __restrict__ py = yd + base;
            const float* __restrict__ pt = td + base;
#pragma unroll
            for (int k = 0; k < 8; k++)
                x[k] = cpack(py[64 * k], pt[64 * k]);
        } else {
#pragma unroll
            for (int k = 0; k < 8; k++) {
                int j = reflect_idx(base + 64 * k, T);
                x[k] = cpack(yd[j], td[j]);
            }
        }
    } else {
#pragma unroll
        for (int k = 0; k < 8; k++) x[k] = 0ull;
    }

    // ---- Stage A ----
    dft8p(x, NEG1, PMI, CC);
    {
        float wr[8], wi[8], s, c;
        __sincosf(-(float)lt * (TWO_PI_F / 512.0f), &s, &c);
        build7(c, s, wr, wi);
#pragma unroll
        for (int v = 1; v < 8; v++) x[v] = ctws(x[v], wr[v], wi[v]);
    }
#pragma unroll
    for (int v = 0; v < 8; v++) sZ[fl][v * 73 + lt] = x[v];
    __syncthreads();

    // ---- Stage B ----
    const int v2 = lt >> 3;
    const int t1 = lt & 7;
#pragma unroll
    for (int t2 = 0; t2 < 8; t2++) x[t2] = sZ[fl][v2 * 73 + t1 + 8 * t2];
    dft8p(x, NEG1, PMI, CC);
    {
        float wr[8], wi[8], s, c;
        __sincosf(-(float)t1 * (TWO_PI_F / 64.0f), &s, &c);
        build7(c, s, wr, wi);
#pragma unroll
        for (int m1 = 1; m1 < 8; m1++) x[m1] = ctws(x[m1], wr[m1], wi[m1]);
    }
    __syncthreads();
#pragma unroll
    for (int m1 = 0; m1 < 8; m1++) {
        int r = v2 * 8 + m1;
        sZ[fl][r * 9 + 2 * v2 + t1] = x[m1];
    }
    __syncthreads();

    // ---- Stage C ----
    {
        const int rowbase = lt * 9 + 2 * (lt >> 3);
#pragma unroll
        for (int k = 0; k < 8; k++) x[k] = sZ[fl][rowbase + k];
    }
    dft8p(x, NEG1, PMI, CC);
    __syncthreads();
    {
        const int fbase = ((lt & 7) << 3) | (lt >> 3);
#pragma unroll
        for (int m2 = 0; m2 < 8; m2++)
            sZ[fl][sw_addr(64 * m2 + fbase)] = x[m2];
    }
    __syncthreads();

    // ---- epilogue: d = angle(Y*conj(T)); inline ip + gd; publish last row ----
    float s_ip = 0.0f, s_gd = 0.0f, s_iaf = 0.0f;
    const int tid = threadIdx.x;
    const int lane = tid & 31;

    if (active) {
        const size_t obase = (size_t)b * ROWSTRIDE;
#pragma unroll
        for (int j = 0; j < 4; j++) {
            int f = lt + 64 * j;
            float zkr, zki, znr, zni;
            cunpack(sZ[fl][sw_addr(f)], zkr, zki);
            int m = (N_FFT - f) & (N_FFT - 1);
            cunpack(sZ[fl][sw_addr(m)], znr, zni);
            float yre = zkr + znr;
            float yim = zki - zni;
            float tre = zki + zni;
            float tim = znr - zkr;
            float pre = yre * tre + yim * tim;
            float pim = yim * tre - yre * tim;
            float d = fast_atan2f(pim, pre);
            dBuf[fl][f] = d;
            if (fl == FPC - 1) g_last[obase + f] = d;
            s_ip += anti_wrap(d);
            float dp = __shfl_up_sync(0xFFFFFFFFu, d, 1);
            if (lane != 0) s_gd += anti_wrap(dp - d);
        }
        if (lt == 0) {   // bin 256 (self-mirror: Y,T real)
            float zkr, zki;
            cunpack(sZ[fl][sw_addr(256)], zkr, zki);
            float pre = 4.0f * zkr * zki;
            float d = fast_atan2f(0.0f, pre);
            dBuf[fl][256] = d;
            if (fl == FPC - 1) g_last[obase + 256] = d;
            s_ip += anti_wrap(d);
        }
    }
    __syncthreads();

    // ---- publish own last row BEFORE any waiting (no cascade) ----
    if (tid == 0) {
        __threadfence();
        atomicExch(&g_flag[b], 1u);
    }

    // ---- deferred gd (f multiples of 32; threads 0..35) ----
    if (tid < 9 * FPC) {
        int fl2 = tid / 9;
        int k = tid - 9 * fl2;
        if (b * FPC + fl2 < n_frames) {
            int f = 32 * k;
            float d0 = dBuf[fl2][f];
            float g = (f == 0) ? d0 : (dBuf[fl2][f - 1] - d0);
            s_gd += anti_wrap(g);
        }
    }

    // ---- bin-256 intra-CTA iaf pairs (threads 36..38) ----
    if (tid >= 36 && tid < 36 + FPC - 1) {
        int fl2 = tid - 35;
        if (b * FPC + fl2 < n_frames)
            s_iaf += anti_wrap(dBuf[fl2 - 1][256] - dBuf[fl2][256]);
    }

    // ---- iaf intra-CTA pairs, bins 0..255 ----
    {
        float dprev = dBuf[0][tid];
#pragma unroll
        for (int fl2 = 1; fl2 < FPC; fl2++) {
            if (b * FPC + fl2 < n_frames) {
                float dc = dBuf[fl2][tid];
                s_iaf += anti_wrap(dprev - dc);
                dprev = dc;
            }
        }
    }

    // ---- cross-CTA iaf via look-back (strictly backward dependency) ----
    if (b > 0) {
        if (tid == 0) {
            while (atomicAdd(&g_flag[b - 1], 0u) == 0u) { __nanosleep(64); }
        }
        __syncthreads();
        __threadfence();
        const size_t pbase = (size_t)(b - 1) * ROWSTRIDE;
        s_iaf += anti_wrap(g_last[pbase + tid] - dBuf[0][tid]);
        if (tid == 0)
            s_iaf += anti_wrap(g_last[pbase + 256] - dBuf[0][256]);
        __syncthreads();
        if (tid == 0) atomicExch(&g_flag[b - 1], 0u);   // reset for next replay
    } else {
        // t = 0 column: iaf term is aw(d[0][f])
        s_iaf += anti_wrap(dBuf[0][tid]);
        if (tid == 0) s_iaf += anti_wrap(dBuf[0][256]);
    }

    // ---- reduce + accumulate + ticket finalize ----
#pragma unroll
    for (int o = 16; o > 0; o >>= 1) {
        s_ip  += __shfl_down_sync(0xFFFFFFFFu, s_ip,  o);
        s_gd  += __shfl_down_sync(0xFFFFFFFFu, s_gd,  o);
        s_iaf += __shfl_down_sync(0xFFFFFFFFu, s_iaf, o);
    }
    if (lane == 0) {
        wsum[tid >> 5][0] = s_ip;
        wsum[tid >> 5][1] = s_gd;
        wsum[tid >> 5][2] = s_iaf;
    }
    __syncthreads();
    if (tid == 0) {
        double a0 = 0.0, a1 = 0.0, a2 = 0.0;
#pragma unroll
        for (int w = 0; w < 8; w++) {
            a0 += (double)wsum[w][0];
            a1 += (double)wsum[w][1];
            a2 += (double)wsum[w][2];
        }
        atomicAdd(&g_acc[0], a0);
        atomicAdd(&g_acc[1], a1);
        atomicAdd(&g_acc[2], a2);
        __threadfence();
        unsigned int ticket = atomicAdd(&g_done, 1u);
        if (ticket == (unsigned)n_cta - 1u) {
            double cnt = (double)n_frames * (double)NBINS;
            volatile double* acc = g_acc;
            out[0] = (float)(acc[0] / cnt);
            out[1] = (float)(acc[1] / cnt);
            out[2] = (float)(acc[2] / cnt);
            g_acc[0] = 0.0; g_acc[1] = 0.0; g_acc[2] = 0.0;
            g_done = 0u;
            atomicExch(&g_flag[n_cta - 1], 0u);   // last flag has no consumer
            __threadfence();
        }
    }
}

extern "C" void kernel_launch(void* const* d_in, const int* in_sizes, int n_in,
                              void* d_out, int out_size) {
    const float* yd = (const float*)d_in[0];
    const float* td = (const float*)d_in[1];
    const int T = in_sizes[0];

    int n_frames = T / HOP + 1;
    if (n_frames > MAX_FRAMES) n_frames = MAX_FRAMES;
    int n_cta = (n_frames + FPC - 1) / FPC;

    fft_phase_kernel<<<n_cta, 256>>>(yd, td, (float*)d_out, T, n_frames, n_cta);
}

// round 13
// speedup vs baseline: 1.1752x; 1.1752x over previous
#include <cuda_runtime.h>
#include <cuda_fp16.h>
#include <math.h>

#define N_FFT 512
#define HOP 128
#define NBINS 257
#define ROWSTRIDE 264            // halves; 528B rows, 16B-aligned
#define MAX_FRAMES 32769
#define FPC 4
#define MAX_CTAS ((MAX_FRAMES + FPC - 1) / FPC)
#define TWO_PI_F 6.28318530717958647692f

__device__ __half g_first[(size_t)MAX_CTAS * ROWSTRIDE];
__device__ __half g_last[(size_t)MAX_CTAS * ROWSTRIDE];
__device__ double g_acc[3];          // zero-init at load; self-cleaned each call
__device__ unsigned int g_done;      // ticket; self-cleaned

// ---------------- packed complex (f32x2) helpers ----------------
typedef unsigned long long cplx;     // lo = re, hi = im

__device__ __forceinline__ cplx cpack(float re, float im) {
    cplx r; asm("mov.b64 %0, {%1, %2};" : "=l"(r) : "f"(re), "f"(im)); return r;
}
__device__ __forceinline__ void cunpack(cplx a, float& re, float& im) {
    asm("mov.b64 {%0, %1}, %2;" : "=f"(re), "=f"(im) : "l"(a));
}
__device__ __forceinline__ cplx cswap(cplx a) {
    cplx r;
    asm("{\n\t.reg .f32 lo, hi;\n\tmov.b64 {lo, hi}, %1;\n\tmov.b64 %0, {hi, lo};\n\t}"
        : "=l"(r) : "l"(a));
    return r;
}
__device__ __forceinline__ cplx cadd2(cplx a, cplx b) {
    cplx r; asm("add.rn.f32x2 %0, %1, %2;" : "=l"(r) : "l"(a), "l"(b)); return r;
}
__device__ __forceinline__ cplx cmul2(cplx a, cplx b) {
    cplx r; asm("mul.rn.f32x2 %0, %1, %2;" : "=l"(r) : "l"(a), "l"(b)); return r;
}
__device__ __forceinline__ cplx cfma2(cplx a, cplx b, cplx c) {
    cplx r; asm("fma.rn.f32x2 %0, %1, %2, %3;" : "=l"(r) : "l"(a), "l"(b), "l"(c)); return r;
}
__device__ __forceinline__ float fneg(float x) {
    return __int_as_float(__float_as_int(x) ^ 0x80000000);
}

__device__ __forceinline__ int reflect_idx(int j, int T) {
    j = abs(j);
    if (j >= T) j = 2 * T - 2 - j;
    return j;
}

__device__ __forceinline__ float anti_wrap(float x) {
    return fabsf(fmaf(-rintf(x * (1.0f / TWO_PI_F)), TWO_PI_F, x));
}

// fast atan2: deg-11 odd minimax poly, max abs err ~2e-6
__device__ __forceinline__ float fast_atan2f(float y, float x) {
    float ax = fabsf(x), ay = fabsf(y);
    float mx = fmaxf(ax, ay), mn = fminf(ax, ay);
    float a = __fdividef(mn, mx);
    float s = a * a;
    float r = -0.0117212f;
    r = fmaf(r, s,  0.05265332f);
    r = fmaf(r, s, -0.11643287f);
    r = fmaf(r, s,  0.19354346f);
    r = fmaf(r, s, -0.33262347f);
    r = fmaf(r, s,  0.99997726f);
    r = r * a;
    if (ay > ax) r = 1.57079632679f - r;
    if (x < 0.0f) r = 3.14159265359f - r;
    return copysignf(r, y);
}

__device__ __forceinline__ void cmuls(float ar, float ai, float br, float bi,
                                      float& cr, float& ci) {
    cr = fmaf(ar, br, -ai * bi);
    ci = fmaf(ar, bi,  ai * br);
}

__device__ __forceinline__ void build7(float w1r, float w1i,
                                       float wr[8], float wi[8]) {
    wr[1] = w1r; wi[1] = w1i;
    cmuls(w1r, w1i, w1r, w1i, wr[2], wi[2]);
    cmuls(wr[2], wi[2], w1r, w1i, wr[3], wi[3]);
    cmuls(wr[2], wi[2], wr[2], wi[2], wr[4], wi[4]);
    cmuls(wr[3], wi[3], wr[2], wi[2], wr[5], wi[5]);
    cmuls(wr[3], wi[3], wr[3], wi[3], wr[6], wi[6]);
    cmuls(wr[4], wi[4], wr[3], wi[3], wr[7], wi[7]);
}

__device__ __forceinline__ void dft8p(cplx x[8], cplx NEG1, cplx PMI, cplx CC) {
    cplx s0 = cadd2(x[0], x[4]);
    cplx s1 = cadd2(x[1], x[5]);
    cplx s2 = cadd2(x[2], x[6]);
    cplx s3 = cadd2(x[3], x[7]);
    cplx u0 = cfma2(x[4], NEG1, x[0]);
    cplx u1 = cfma2(x[5], NEG1, x[1]);
    cplx u2 = cfma2(x[6], NEG1, x[2]);
    cplx u3 = cfma2(x[7], NEG1, x[3]);

    cplx t1 = cmul2(CC, cfma2(cswap(u1), PMI, u1));
    cplx t2 = cmul2(cswap(u2), PMI);
    cplx t3 = cmul2(CC, cfma2(u3, NEG1, cmul2(cswap(u3), PMI)));

    cplx e0 = cadd2(s0, s2);
    cplx e2 = cfma2(s2, NEG1, s0);
    cplx e1 = cadd2(s1, s3);
    cplx d13 = cfma2(s3, NEG1, s1);
    cplx e3 = cmul2(cswap(d13), PMI);
    x[0] = cadd2(e0, e1);
    x[4] = cfma2(e1, NEG1, e0);
    x[2] = cadd2(e2, e3);
    x[6] = cfma2(e3, NEG1, e2);

    cplx o0 = cadd2(u0, t2);
    cplx o2 = cfma2(t2, NEG1, u0);
    cplx o1 = cadd2(t1, t3);
    cplx d13b = cfma2(t3, NEG1, t1);
    cplx o3 = cmul2(cswap(d13b), PMI);
    x[1] = cadd2(o0, o1);
    x[5] = cfma2(o1, NEG1, o0);
    x[3] = cadd2(o2, o3);
    x[7] = cfma2(o3, NEG1, o2);
}

__device__ __forceinline__ cplx ctws(cplx x, float wr, float wi) {
    cplx wrr = cpack(wr, wr);
    cplx wim = cpack(fneg(wi), wi);
    return cfma2(cswap(x), wim, cmul2(x, wrr));
}

__device__ __forceinline__ int sw_addr(int f) {
    return f ^ ((f >> 3) & 7);
}

// 4 frames per 256-thread CTA; radix-8^3 packed-register FFT; fused loss sums.
// Smem layouts: stage A/B stride 72 (2-way optimal for 64-bit LDS),
// stage B store / C load plain stride 9 (2-way optimal, 9 coprime 16).
__global__ __launch_bounds__(256) void fft_phase_kernel(
    const float* __restrict__ yd, const float* __restrict__ td,
    int T, int n_frames)
{
    __shared__ cplx sZ[FPC][576];
    __shared__ float dBuf[FPC][260];
    __shared__ float wsum[8][3];

    const int lt = threadIdx.x & 63;
    const int fl = threadIdx.x >> 6;
    const int frame = blockIdx.x * FPC + fl;
    const bool active = (frame < n_frames);

    const cplx NEG1 = cpack(-1.0f, -1.0f);
    const cplx PMI  = cpack(1.0f, -1.0f);
    const cplx CC   = cpack(0.70710678118654752440f, 0.70710678118654752440f);

    cplx x[8];

    // ---- load (fast interior path skips all reflect logic) ----
    if (active) {
        const int base = frame * HOP - (N_FFT / 2) + lt;
        if (frame >= 2 && frame * HOP + 256 <= T) {
            const float* __restrict__ py = yd + base;
            const float* __restrict__ pt = td + base;
#pragma unroll
            for (int k = 0; k < 8; k++)
                x[k] = cpack(py[64 * k], pt[64 * k]);
        } else {
#pragma unroll
            for (int k = 0; k < 8; k++) {
                int j = reflect_idx(base + 64 * k, T);
                x[k] = cpack(yd[j], td[j]);
            }
        }
    } else {
#pragma unroll
        for (int k = 0; k < 8; k++) x[k] = 0ull;
    }

    // ---- Stage A: dft8 over k, twiddle W512^{lt*v} ----
    dft8p(x, NEG1, PMI, CC);
    {
        float wr[8], wi[8], s, c;
        __sincosf(-(float)lt * (TWO_PI_F / 512.0f), &s, &c);
        build7(c, s, wr, wi);
#pragma unroll
        for (int v = 1; v < 8; v++) x[v] = ctws(x[v], wr[v], wi[v]);
    }
#pragma unroll
    for (int v = 0; v < 8; v++) sZ[fl][v * 72 + lt] = x[v];
    __syncthreads();

    // ---- Stage B: dft8 over t2, twiddle W64^{t1*m1} ----
    const int v2 = lt >> 3;
    const int t1 = lt & 7;
#pragma unroll
    for (int t2 = 0; t2 < 8; t2++) x[t2] = sZ[fl][v2 * 72 + t1 + 8 * t2];
    dft8p(x, NEG1, PMI, CC);
    {
        float wr[8], wi[8], s, c;
        __sincosf(-(float)t1 * (TWO_PI_F / 64.0f), &s, &c);
        build7(c, s, wr, wi);
#pragma unroll
        for (int m1 = 1; m1 < 8; m1++) x[m1] = ctws(x[m1], wr[m1], wi[m1]);
    }
    __syncthreads();
#pragma unroll
    for (int m1 = 0; m1 < 8; m1++)
        sZ[fl][(v2 * 8 + m1) * 9 + t1] = x[m1];
    __syncthreads();

    // ---- Stage C ----
    {
        const int rowbase = lt * 9;
#pragma unroll
        for (int k = 0; k < 8; k++) x[k] = sZ[fl][rowbase + k];
    }
    dft8p(x, NEG1, PMI, CC);
    __syncthreads();
    {
        const int fbase = ((lt & 7) << 3) | (lt >> 3);  // 8*m1 + v
#pragma unroll
        for (int m2 = 0; m2 < 8; m2++)
            sZ[fl][sw_addr(64 * m2 + fbase)] = x[m2];
    }
    __syncthreads();

    // ---- epilogue: split spectrum, d = angle(Y*conj(T)); inline ip + gd ----
    float s_ip = 0.0f, s_gd = 0.0f, s_iaf = 0.0f;
    const int tid = threadIdx.x;
    const int lane = tid & 31;

    if (active) {
        const size_t obase = (size_t)blockIdx.x * ROWSTRIDE;
#pragma unroll
        for (int j = 0; j < 4; j++) {
            int f = lt + 64 * j;
            float zkr, zki, znr, zni;
            cunpack(sZ[fl][sw_addr(f)], zkr, zki);
            int m = (N_FFT - f) & (N_FFT - 1);
            cunpack(sZ[fl][sw_addr(m)], znr, zni);
            float yre = zkr + znr;
            float yim = zki - zni;
            float tre = zki + zni;
            float tim = znr - zkr;
            float pre = yre * tre + yim * tim;
            float pim = yim * tre - yre * tim;
            float d = fast_atan2f(pim, pre);
            dBuf[fl][f] = d;
            if (fl == 0) g_first[obase + f] = __float2half_rn(d);
            if (fl == FPC - 1) g_last[obase + f] = __float2half_rn(d);
            s_ip += anti_wrap(d);
            float dp = __shfl_up_sync(0xFFFFFFFFu, d, 1);
            if (lane != 0) s_gd += anti_wrap(dp - d);
        }
        if (lt == 0) {   // bin 256 (self-mirror: Y,T real)
            float zkr, zki;
            cunpack(sZ[fl][sw_addr(256)], zkr, zki);
            float pre = 4.0f * zkr * zki;
            float d = fast_atan2f(0.0f, pre);
            dBuf[fl][256] = d;
            if (fl == 0) g_first[obase + 256] = __float2half_rn(d);
            if (fl == FPC - 1) g_last[obase + 256] = __float2half_rn(d);
            s_ip += anti_wrap(d);
        }
    }
    __syncthreads();

    // ---- deferred gd (f multiples of 32; threads 0..35) ----
    if (tid < 9 * FPC) {
        int fl2 = tid / 9;
        int k = tid - 9 * fl2;
        if (blockIdx.x * FPC + fl2 < n_frames) {
            int f = 32 * k;
            float d0 = dBuf[fl2][f];
            float g = (f == 0) ? d0 : (dBuf[fl2][f - 1] - d0);
            s_gd += anti_wrap(g);
        }
    }

    // ---- bin-256 intra-CTA iaf pairs (threads 36..38) ----
    if (tid >= 36 && tid < 36 + FPC - 1) {
        int fl2 = tid - 35;
        if (blockIdx.x * FPC + fl2 < n_frames)
            s_iaf += anti_wrap(dBuf[fl2 - 1][256] - dBuf[fl2][256]);
    }

    // ---- iaf intra-CTA pairs, bins 0..255 ----
    {
        float dprev = dBuf[0][tid];
#pragma unroll
        for (int fl2 = 1; fl2 < FPC; fl2++) {
            if (blockIdx.x * FPC + fl2 < n_frames) {
                float dc = dBuf[fl2][tid];
                s_iaf += anti_wrap(dprev - dc);
                dprev = dc;
            }
        }
    }

#pragma unroll
    for (int o = 16; o > 0; o >>= 1) {
        s_ip  += __shfl_down_sync(0xFFFFFFFFu, s_ip,  o);
        s_gd  += __shfl_down_sync(0xFFFFFFFFu, s_gd,  o);
        s_iaf += __shfl_down_sync(0xFFFFFFFFu, s_iaf, o);
    }
    if (lane == 0) {
        wsum[tid >> 5][0] = s_ip;
        wsum[tid >> 5][1] = s_gd;
        wsum[tid >> 5][2] = s_iaf;
    }
    __syncthreads();
    if (tid == 0) {
        double a0 = 0.0, a1 = 0.0, a2 = 0.0;
#pragma unroll
        for (int w = 0; w < 8; w++) {
            a0 += (double)wsum[w][0];
            a1 += (double)wsum[w][1];
            a2 += (double)wsum[w][2];
        }
        atomicAdd(&g_acc[0], a0);
        atomicAdd(&g_acc[1], a1);
        atomicAdd(&g_acc[2], a2);
    }
}

// Boundary iaf terms + finalize. fp16 rows: 16B load = 8 bins; 32 chunks/row.
__global__ __launch_bounds__(256) void boundary_finalize_kernel(
    float* __restrict__ out, int n_frames, int n_rows)
{
    __shared__ float wsum[8];
    float s = 0.0f;
    const int tid = threadIdx.x;
    const int c = tid & 31;       // 16B chunk 0..31 (covers bins 0..255)
    const int rloc = tid >> 5;    // row-in-group 0..7

    for (int b = blockIdx.x * 8 + rloc; b < n_rows; b += gridDim.x * 8) {
        const uint4* __restrict__ rowF =
            (const uint4*)(g_first + (size_t)b * ROWSTRIDE);
        uint4 fu = rowF[c];
        __half2 fh[4] = {
            *(__half2*)&fu.x, *(__half2*)&fu.y, *(__half2*)&fu.z, *(__half2*)&fu.w };
        if (b == 0) {
#pragma unroll
            for (int q = 0; q < 4; q++) {
                float2 fv = __half22float2(fh[q]);
                s += anti_wrap(fv.x) + anti_wrap(fv.y);
            }
            if (c == 0) s += anti_wrap(__half2float(g_first[256]));
        } else {
            const uint4* __restrict__ rowL =
                (const uint4*)(g_last + (size_t)(b - 1) * ROWSTRIDE);
            uint4 lu = rowL[c];
            __half2 lh[4] = {
                *(__half2*)&lu.x, *(__half2*)&lu.y, *(__half2*)&lu.z, *(__half2*)&lu.w };
#pragma unroll
            for (int q = 0; q < 4; q++) {
                float2 fv = __half22float2(fh[q]);
                float2 lv = __half22float2(lh[q]);
                s += anti_wrap(lv.x - fv.x) + anti_wrap(lv.y - fv.y);
            }
            if (c == 0)
                s += anti_wrap(__half2float(g_last[(size_t)(b - 1) * ROWSTRIDE + 256])
                             - __half2float(g_first[(size_t)b * ROWSTRIDE + 256]));
        }
    }

#pragma unroll
    for (int o = 16; o > 0; o >>= 1)
        s += __shfl_down_sync(0xFFFFFFFFu, s, o);
    if ((tid & 31) == 0) wsum[tid >> 5] = s;
    __syncthreads();

    if (tid == 0) {
        double a = 0.0;
#pragma unroll
        for (int w = 0; w < 8; w++) a += (double)wsum[w];
        atomicAdd(&g_acc[2], a);
        __threadfence();
        unsigned int ticket = atomicAdd(&g_done, 1u);
        if (ticket == gridDim.x - 1) {
            double cnt = (double)n_frames * (double)NBINS;
            volatile double* acc = g_acc;
            out[0] = (float)(acc[0] / cnt);
            out[1] = (float)(acc[1] / cnt);
            out[2] = (float)(acc[2] / cnt);
            g_acc[0] = 0.0; g_acc[1] = 0.0; g_acc[2] = 0.0;
            g_done = 0u;
            __threadfence();
        }
    }
}

extern "C" void kernel_launch(void* const* d_in, const int* in_sizes, int n_in,
                              void* d_out, int out_size) {
    const float* yd = (const float*)d_in[0];
    const float* td = (const float*)d_in[1];
    const int T = in_sizes[0];

    int n_frames = T / HOP + 1;
    if (n_frames > MAX_FRAMES) n_frames = MAX_FRAMES;
    int n_cta = (n_frames + FPC - 1) / FPC;

    fft_phase_kernel<<<n_cta, 256>>>(yd, td, T, n_frames);
    boundary_finalize_kernel<<<512, 256>>>((float*)d_out, n_frames, n_cta);
}

// round 14
// speedup vs baseline: 1.3313x; 1.1328x over previous
#include <cuda_runtime.h>
#include <cuda_fp16.h>
#include <math.h>

#define N_FFT 512
#define HOP 128
#define NBINS 257
#define ROWSTRIDE 264            // halves; 528B rows, 16B-aligned
#define MAX_FRAMES 32769
#define FPC 4
#define MAX_CTAS ((MAX_FRAMES + FPC - 1) / FPC)
#define TWO_PI_F 6.28318530717958647692f

__device__ __half g_first[(size_t)MAX_CTAS * ROWSTRIDE];
__device__ __half g_last[(size_t)MAX_CTAS * ROWSTRIDE];
__device__ double g_acc[3];          // zero-init at load; self-cleaned each call
__device__ unsigned int g_done;      // ticket; self-cleaned

// ---------------- packed complex (f32x2) helpers ----------------
typedef unsigned long long cplx;     // lo = re, hi = im

__device__ __forceinline__ cplx cpack(float re, float im) {
    cplx r; asm("mov.b64 %0, {%1, %2};" : "=l"(r) : "f"(re), "f"(im)); return r;
}
__device__ __forceinline__ void cunpack(cplx a, float& re, float& im) {
    asm("mov.b64 {%0, %1}, %2;" : "=f"(re), "=f"(im) : "l"(a));
}
__device__ __forceinline__ cplx cswap(cplx a) {
    cplx r;
    asm("{\n\t.reg .f32 lo, hi;\n\tmov.b64 {lo, hi}, %1;\n\tmov.b64 %0, {hi, lo};\n\t}"
        : "=l"(r) : "l"(a));
    return r;
}
__device__ __forceinline__ cplx cadd2(cplx a, cplx b) {
    cplx r; asm("add.rn.f32x2 %0, %1, %2;" : "=l"(r) : "l"(a), "l"(b)); return r;
}
__device__ __forceinline__ cplx cmul2(cplx a, cplx b) {
    cplx r; asm("mul.rn.f32x2 %0, %1, %2;" : "=l"(r) : "l"(a), "l"(b)); return r;
}
__device__ __forceinline__ cplx cfma2(cplx a, cplx b, cplx c) {
    cplx r; asm("fma.rn.f32x2 %0, %1, %2, %3;" : "=l"(r) : "l"(a), "l"(b), "l"(c)); return r;
}
__device__ __forceinline__ float fneg(float x) {
    return __int_as_float(__float_as_int(x) ^ 0x80000000);
}

__device__ __forceinline__ int reflect_idx(int j, int T) {
    j = abs(j);
    if (j >= T) j = 2 * T - 2 - j;
    return j;
}

__device__ __forceinline__ float anti_wrap(float x) {
    return fabsf(fmaf(-rintf(x * (1.0f / TWO_PI_F)), TWO_PI_F, x));
}

// fast atan2: deg-11 odd minimax poly, max abs err ~2e-6
__device__ __forceinline__ float fast_atan2f(float y, float x) {
    float ax = fabsf(x), ay = fabsf(y);
    float mx = fmaxf(ax, ay), mn = fminf(ax, ay);
    float a = __fdividef(mn, mx);
    float s = a * a;
    float r = -0.0117212f;
    r = fmaf(r, s,  0.05265332f);
    r = fmaf(r, s, -0.11643287f);
    r = fmaf(r, s,  0.19354346f);
    r = fmaf(r, s, -0.33262347f);
    r = fmaf(r, s,  0.99997726f);
    r = r * a;
    if (ay > ax) r = 1.57079632679f - r;
    if (x < 0.0f) r = 3.14159265359f - r;
    return copysignf(r, y);
}

__device__ __forceinline__ void cmuls(float ar, float ai, float br, float bi,
                                      float& cr, float& ci) {
    cr = fmaf(ar, br, -ai * bi);
    ci = fmaf(ar, bi,  ai * br);
}

__device__ __forceinline__ void build7(float w1r, float w1i,
                                       float wr[8], float wi[8]) {
    wr[1] = w1r; wi[1] = w1i;
    cmuls(w1r, w1i, w1r, w1i, wr[2], wi[2]);
    cmuls(wr[2], wi[2], w1r, w1i, wr[3], wi[3]);
    cmuls(wr[2], wi[2], wr[2], wi[2], wr[4], wi[4]);
    cmuls(wr[3], wi[3], wr[2], wi[2], wr[5], wi[5]);
    cmuls(wr[3], wi[3], wr[3], wi[3], wr[6], wi[6]);
    cmuls(wr[4], wi[4], wr[3], wi[3], wr[7], wi[7]);
}

__device__ __forceinline__ void dft8p(cplx x[8], cplx NEG1, cplx PMI, cplx CC) {
    cplx s0 = cadd2(x[0], x[4]);
    cplx s1 = cadd2(x[1], x[5]);
    cplx s2 = cadd2(x[2], x[6]);
    cplx s3 = cadd2(x[3], x[7]);
    cplx u0 = cfma2(x[4], NEG1, x[0]);
    cplx u1 = cfma2(x[5], NEG1, x[1]);
    cplx u2 = cfma2(x[6], NEG1, x[2]);
    cplx u3 = cfma2(x[7], NEG1, x[3]);

    cplx t1 = cmul2(CC, cfma2(cswap(u1), PMI, u1));
    cplx t2 = cmul2(cswap(u2), PMI);
    cplx t3 = cmul2(CC, cfma2(u3, NEG1, cmul2(cswap(u3), PMI)));

    cplx e0 = cadd2(s0, s2);
    cplx e2 = cfma2(s2, NEG1, s0);
    cplx e1 = cadd2(s1, s3);
    cplx d13 = cfma2(s3, NEG1, s1);
    cplx e3 = cmul2(cswap(d13), PMI);
    x[0] = cadd2(e0, e1);
    x[4] = cfma2(e1, NEG1, e0);
    x[2] = cadd2(e2, e3);
    x[6] = cfma2(e3, NEG1, e2);

    cplx o0 = cadd2(u0, t2);
    cplx o2 = cfma2(t2, NEG1, u0);
    cplx o1 = cadd2(t1, t3);
    cplx d13b = cfma2(t3, NEG1, t1);
    cplx o3 = cmul2(cswap(d13b), PMI);
    x[1] = cadd2(o0, o1);
    x[5] = cfma2(o1, NEG1, o0);
    x[3] = cadd2(o2, o3);
    x[7] = cfma2(o3, NEG1, o2);
}

__device__ __forceinline__ cplx ctws(cplx x, float wr, float wi) {
    cplx wrr = cpack(wr, wr);
    cplx wim = cpack(fneg(wi), wi);
    return cfma2(cswap(x), wim, cmul2(x, wrr));
}

__device__ __forceinline__ int sw_addr(int f) {
    return f ^ ((f >> 3) & 7);
}

// 4 frames per 256-thread CTA; radix-8^3 packed-register FFT; fused loss sums.
// Register epilogue: only mirror bins {0} u [256,511] go through smem.
__global__ __launch_bounds__(256) void fft_phase_kernel(
    const float* __restrict__ yd, const float* __restrict__ td,
    int T, int n_frames)
{
    __shared__ cplx sZ[FPC][576];
    __shared__ float dBuf[FPC][260];
    __shared__ float wsum[8][3];

    const int lt = threadIdx.x & 63;
    const int fl = threadIdx.x >> 6;
    const int frame = blockIdx.x * FPC + fl;
    const bool active = (frame < n_frames);

    const cplx NEG1 = cpack(-1.0f, -1.0f);
    const cplx PMI  = cpack(1.0f, -1.0f);
    const cplx CC   = cpack(0.70710678118654752440f, 0.70710678118654752440f);

    cplx x[8];

    // ---- load (fast interior path skips all reflect logic) ----
    if (active) {
        const int base = frame * HOP - (N_FFT / 2) + lt;
        if (frame >= 2 && frame * HOP + 256 <= T) {
            const float* __restrict__ py = yd + base;
            const float* __restrict__ pt = td + base;
#pragma unroll
            for (int k = 0; k < 8; k++)
                x[k] = cpack(py[64 * k], pt[64 * k]);
        } else {
#pragma unroll
            for (int k = 0; k < 8; k++) {
                int j = reflect_idx(base + 64 * k, T);
                x[k] = cpack(yd[j], td[j]);
            }
        }
    } else {
#pragma unroll
        for (int k = 0; k < 8; k++) x[k] = 0ull;
    }

    // ---- Stage A: dft8 over k, twiddle W512^{lt*v} ----
    dft8p(x, NEG1, PMI, CC);
    {
        float wr[8], wi[8], s, c;
        __sincosf(-(float)lt * (TWO_PI_F / 512.0f), &s, &c);
        build7(c, s, wr, wi);
#pragma unroll
        for (int v = 1; v < 8; v++) x[v] = ctws(x[v], wr[v], wi[v]);
    }
#pragma unroll
    for (int v = 0; v < 8; v++) sZ[fl][v * 72 + lt] = x[v];
    __syncthreads();

    // ---- Stage B: dft8 over t2, twiddle W64^{t1*m1} ----
    const int v2 = lt >> 3;
    const int t1 = lt & 7;
#pragma unroll
    for (int t2 = 0; t2 < 8; t2++) x[t2] = sZ[fl][v2 * 72 + t1 + 8 * t2];
    dft8p(x, NEG1, PMI, CC);
    {
        float wr[8], wi[8], s, c;
        __sincosf(-(float)t1 * (TWO_PI_F / 64.0f), &s, &c);
        build7(c, s, wr, wi);
#pragma unroll
        for (int m1 = 1; m1 < 8; m1++) x[m1] = ctws(x[m1], wr[m1], wi[m1]);
    }
    __syncthreads();
#pragma unroll
    for (int m1 = 0; m1 < 8; m1++)
        sZ[fl][(v2 * 8 + m1) * 9 + t1] = x[m1];
    __syncthreads();

    // ---- Stage C ----
    {
        const int rowbase = lt * 9;
#pragma unroll
        for (int k = 0; k < 8; k++) x[k] = sZ[fl][rowbase + k];
    }
    dft8p(x, NEG1, PMI, CC);
    __syncthreads();
    // x[m2] = X[64*m2 + fbase]. Store ONLY mirror bins: m2>=4 plus bin 0.
    const int fbase = ((lt & 7) << 3) | (lt >> 3);  // 8*m1 + v
    {
#pragma unroll
        for (int m2 = 4; m2 < 8; m2++)
            sZ[fl][sw_addr(64 * m2 + fbase)] = x[m2];
        if (fbase == 0) sZ[fl][0] = x[0];
    }
    __syncthreads();

    // ---- epilogue: Zk from registers, mirror Zn from smem; ip inline ----
    float s_ip = 0.0f, s_gd = 0.0f, s_iaf = 0.0f;
    const int tid = threadIdx.x;
    const int lane = tid & 31;

    if (active) {
        const size_t obase = (size_t)blockIdx.x * ROWSTRIDE;
#pragma unroll
        for (int m2 = 0; m2 < 4; m2++) {
            int f = 64 * m2 + fbase;   // 0..255
            float zkr, zki, znr, zni;
            cunpack(x[m2], zkr, zki);
            cunpack(sZ[fl][sw_addr((N_FFT - f) & (N_FFT - 1))], znr, zni);
            float yre = zkr + znr;
            float yim = zki - zni;
            float tre = zki + zni;
            float tim = znr - zkr;
            float pre = yre * tre + yim * tim;
            float pim = yim * tre - yre * tim;
            float d = fast_atan2f(pim, pre);
            dBuf[fl][f] = d;
            if (fl == 0) g_first[obase + f] = __float2half_rn(d);
            if (fl == FPC - 1) g_last[obase + f] = __float2half_rn(d);
            s_ip += anti_wrap(d);
        }
        if (fbase == 0) {   // bin 256 from register x[4] (self-mirror: Y,T real)
            float zkr, zki;
            cunpack(x[4], zkr, zki);
            float pre = 4.0f * zkr * zki;
            float d = fast_atan2f(0.0f, pre);
            dBuf[fl][256] = d;
            if (fl == 0) g_first[obase + 256] = __float2half_rn(d);
            if (fl == FPC - 1) g_last[obase + 256] = __float2half_rn(d);
            s_ip += anti_wrap(d);
        }
    }
    __syncthreads();

    // ---- deferred gd (f multiples of 32 incl. 256; threads 0..35) ----
    if (tid < 9 * FPC) {
        int fl2 = tid / 9;
        int k = tid - 9 * fl2;
        if (blockIdx.x * FPC + fl2 < n_frames) {
            int f = 32 * k;
            float d0 = dBuf[fl2][f];
            float g = (f == 0) ? d0 : (dBuf[fl2][f - 1] - d0);
            s_gd += anti_wrap(g);
        }
    }

    // ---- bin-256 intra-CTA iaf pairs (threads 36..38) ----
    if (tid >= 36 && tid < 36 + FPC - 1) {
        int fl2 = tid - 35;
        if (blockIdx.x * FPC + fl2 < n_frames)
            s_iaf += anti_wrap(dBuf[fl2 - 1][256] - dBuf[fl2][256]);
    }

    // ---- gd (f%32!=0 via shuffle) + iaf intra-CTA pairs, bins 0..255 ----
    {
        float dprev = 0.0f;
#pragma unroll
        for (int fl2 = 0; fl2 < FPC; fl2++) {
            if (blockIdx.x * FPC + fl2 < n_frames) {
                float dc = dBuf[fl2][tid];
                float dp = __shfl_up_sync(0xFFFFFFFFu, dc, 1);
                if (lane != 0) s_gd += anti_wrap(dp - dc);
                if (fl2 > 0) s_iaf += anti_wrap(dprev - dc);
                dprev = dc;
            }
        }
    }

#pragma unroll
    for (int o = 16; o > 0; o >>= 1) {
        s_ip  += __shfl_down_sync(0xFFFFFFFFu, s_ip,  o);
        s_gd  += __shfl_down_sync(0xFFFFFFFFu, s_gd,  o);
        s_iaf += __shfl_down_sync(0xFFFFFFFFu, s_iaf, o);
    }
    if (lane == 0) {
        wsum[tid >> 5][0] = s_ip;
        wsum[tid >> 5][1] = s_gd;
        wsum[tid >> 5][2] = s_iaf;
    }
    __syncthreads();
    if (tid == 0) {
        double a0 = 0.0, a1 = 0.0, a2 = 0.0;
#pragma unroll
        for (int w = 0; w < 8; w++) {
            a0 += (double)wsum[w][0];
            a1 += (double)wsum[w][1];
            a2 += (double)wsum[w][2];
        }
        atomicAdd(&g_acc[0], a0);
        atomicAdd(&g_acc[1], a1);
        atomicAdd(&g_acc[2], a2);
    }
}

// Boundary iaf terms + finalize. fp16 rows: 16B load = 8 bins; 32 chunks/row.
__global__ __launch_bounds__(256) void boundary_finalize_kernel(
    float* __restrict__ out, int n_frames, int n_rows)
{
    __shared__ float wsum[8];
    float s = 0.0f;
    const int tid = threadIdx.x;
    const int c = tid & 31;       // 16B chunk 0..31 (covers bins 0..255)
    const int rloc = tid >> 5;    // row-in-group 0..7

    for (int b = blockIdx.x * 8 + rloc; b < n_rows; b += gridDim.x * 8) {
        const uint4* __restrict__ rowF =
            (const uint4*)(g_first + (size_t)b * ROWSTRIDE);
        uint4 fu = rowF[c];
        __half2 fh[4] = {
            *(__half2*)&fu.x, *(__half2*)&fu.y, *(__half2*)&fu.z, *(__half2*)&fu.w };
        if (b == 0) {
#pragma unroll
            for (int q = 0; q < 4; q++) {
                float2 fv = __half22float2(fh[q]);
                s += anti_wrap(fv.x) + anti_wrap(fv.y);
            }
            if (c == 0) s += anti_wrap(__half2float(g_first[256]));
        } else {
            const uint4* __restrict__ rowL =
                (const uint4*)(g_last + (size_t)(b - 1) * ROWSTRIDE);
            uint4 lu = rowL[c];
            __half2 lh[4] = {
                *(__half2*)&lu.x, *(__half2*)&lu.y, *(__half2*)&lu.z, *(__half2*)&lu.w };
#pragma unroll
            for (int q = 0; q < 4; q++) {
                float2 fv = __half22float2(fh[q]);
                float2 lv = __half22float2(lh[q]);
                s += anti_wrap(lv.x - fv.x) + anti_wrap(lv.y - fv.y);
            }
            if (c == 0)
                s += anti_wrap(__half2float(g_last[(size_t)(b - 1) * ROWSTRIDE + 256])
                             - __half2float(g_first[(size_t)b * ROWSTRIDE + 256]));
        }
    }

#pragma unroll
    for (int o = 16; o > 0; o >>= 1)
        s += __shfl_down_sync(0xFFFFFFFFu, s, o);
    if ((tid & 31) == 0) wsum[tid >> 5] = s;
    __syncthreads();

    if (tid == 0) {
        double a = 0.0;
#pragma unroll
        for (int w = 0; w < 8; w++) a += (double)wsum[w];
        atomicAdd(&g_acc[2], a);
        __threadfence();
        unsigned int ticket = atomicAdd(&g_done, 1u);
        if (ticket == gridDim.x - 1) {
            double cnt = (double)n_frames * (double)NBINS;
            volatile double* acc = g_acc;
            out[0] = (float)(acc[0] / cnt);
            out[1] = (float)(acc[1] / cnt);
            out[2] = (float)(acc[2] / cnt);
            g_acc[0] = 0.0; g_acc[1] = 0.0; g_acc[2] = 0.0;
            g_done = 0u;
            __threadfence();
        }
    }
}

extern "C" void kernel_launch(void* const* d_in, const int* in_sizes, int n_in,
                              void* d_out, int out_size) {
    const float* yd = (const float*)d_in[0];
    const float* td = (const float*)d_in[1];
    const int T = in_sizes[0];

    int n_frames = T / HOP + 1;
    if (n_frames > MAX_FRAMES) n_frames = MAX_FRAMES;
    int n_cta = (n_frames + FPC - 1) / FPC;

    fft_phase_kernel<<<n_cta, 256>>>(yd, td, T, n_frames);
    boundary_finalize_kernel<<<512, 256>>>((float*)d_out, n_frames, n_cta);
}